// round 6
// baseline (speedup 1.0000x reference)
#include <cuda_runtime.h>
#include <cuda_bf16.h>
#include <cstdint>

#define BB   64
#define TT   512
#define DD   128
#define HH   256
#define G4H  1024

typedef unsigned long long u64;

// ---------------------------------------------------------------------------
// Device scratch
// ---------------------------------------------------------------------------
__device__ float g_Gv[(size_t)BB * TT * G4H];   // time-major: [(t*64+b)*1024 + n]
__device__ float g_Gl[(size_t)BB * TT * G4H];
__device__ float g_Gu[(size_t)BB * TT * G4H];
__device__ float4 g_Hf4[2 * HH * BB];           // [pp][h*BB + b] = (v, m, r, _)
__device__ unsigned int g_bar[8];

// ---------------------------------------------------------------------------
// Helpers
// ---------------------------------------------------------------------------
__device__ __forceinline__ u64 pk(float lo, float hi) {
    u64 r; asm("mov.b64 %0, {%1,%2};" : "=l"(r) : "f"(lo), "f"(hi)); return r;
}
__device__ __forceinline__ u64 fma2(u64 a, u64 b, u64 c) {
    u64 d; asm("fma.rn.f32x2 %0, %1, %2, %3;" : "=l"(d) : "l"(a), "l"(b), "l"(c)); return d;
}
__device__ __forceinline__ u64 add2(u64 a, u64 b) {
    u64 d; asm("add.rn.f32x2 %0, %1, %2;" : "=l"(d) : "l"(a), "l"(b)); return d;
}
__device__ __forceinline__ void upk(u64 v, float& lo, float& hi) {
    asm("mov.b64 {%0,%1}, %2;" : "=f"(lo), "=f"(hi) : "l"(v));
}
__device__ __forceinline__ float sigf(float x) {
    return __fdividef(1.0f, 1.0f + __expf(-x));
}
__device__ __forceinline__ float tanhf_(float x) {
    return __fdividef(2.0f, 1.0f + __expf(-2.0f * x)) - 1.0f;
}
__device__ __forceinline__ float min4f(float a, float b, float c, float d) {
    return fminf(fminf(a, b), fminf(c, d));
}
__device__ __forceinline__ float max4f(float a, float b, float c, float d) {
    return fmaxf(fmaxf(a, b), fmaxf(c, d));
}

// ---------------------------------------------------------------------------
// Kernel 1: gx interval GEMM (FFMA2). Time-major output. Resets barriers.
// ---------------------------------------------------------------------------
#define GM 64
#define GN 64
#define GK 16

__global__ __launch_bounds__(256) void gx_gemm_kernel(
    const float* __restrict__ xv, const float* __restrict__ xl,
    const float* __restrict__ xu, const float* __restrict__ W,
    const float* __restrict__ bias)
{
    if (blockIdx.x == 0 && blockIdx.y == 0 && threadIdx.x < 8)
        g_bar[threadIdx.x] = 0u;

    __shared__ float sAvD[GK][2 * GM + 4];
    __shared__ float sAmD[GK][2 * GM + 4];
    __shared__ float sArD[GK][2 * GM + 4];
    __shared__ float sB [GK][GN + 4];
    __shared__ float sBa[GK][GN + 4];

    const int n0 = blockIdx.x * GN;
    const int m0 = blockIdx.y * GM;
    const int tid = threadIdx.x;
    const int tx = tid & 15;
    const int ty = tid >> 4;

    u64 accv[4][2], accm[4][2], accr[4][2];
#pragma unroll
    for (int i = 0; i < 4; i++)
#pragma unroll
        for (int j = 0; j < 2; j++) { accv[i][j] = 0ull; accm[i][j] = 0ull; accr[i][j] = 0ull; }

    const int ml = tid >> 2;
    const int kq = tid & 3;

    for (int k0 = 0; k0 < DD; k0 += GK) {
        {
            const float4 v4 = *(const float4*)(xv + (size_t)(m0 + ml) * DD + k0 + kq * 4);
            const float4 l4 = *(const float4*)(xl + (size_t)(m0 + ml) * DD + k0 + kq * 4);
            const float4 u4 = *(const float4*)(xu + (size_t)(m0 + ml) * DD + k0 + kq * 4);
            const float vv[4] = {v4.x, v4.y, v4.z, v4.w};
            const float ll[4] = {l4.x, l4.y, l4.z, l4.w};
            const float uu[4] = {u4.x, u4.y, u4.z, u4.w};
#pragma unroll
            for (int j = 0; j < 4; j++) {
                const int k = kq * 4 + j;
                const float mu = 0.5f * (ll[j] + uu[j]);
                const float rr = 0.5f * (uu[j] - ll[j]);
                ((float2*)&sAvD[k][0])[ml] = make_float2(vv[j], vv[j]);
                ((float2*)&sAmD[k][0])[ml] = make_float2(mu, mu);
                ((float2*)&sArD[k][0])[ml] = make_float2(rr, rr);
            }
        }
        {
            const float4 w4 = *(const float4*)(W + (size_t)(n0 + ml) * DD + k0 + kq * 4);
            const float ww[4] = {w4.x, w4.y, w4.z, w4.w};
#pragma unroll
            for (int j = 0; j < 4; j++) {
                sB [kq * 4 + j][ml] = ww[j];
                sBa[kq * 4 + j][ml] = fabsf(ww[j]);
            }
        }
        __syncthreads();

#pragma unroll
        for (int k = 0; k < GK; k++) {
            const u64 b01 = *(const u64*)&sB [k][tx * 4];
            const u64 b23 = *(const u64*)&sB [k][tx * 4 + 2];
            const u64 a01 = *(const u64*)&sBa[k][tx * 4];
            const u64 a23 = *(const u64*)&sBa[k][tx * 4 + 2];
#pragma unroll
            for (int i = 0; i < 4; i++) {
                const u64 av = *(const u64*)&sAvD[k][2 * (4 * ty + i)];
                const u64 am = *(const u64*)&sAmD[k][2 * (4 * ty + i)];
                const u64 ar = *(const u64*)&sArD[k][2 * (4 * ty + i)];
                accv[i][0] = fma2(av, b01, accv[i][0]);
                accv[i][1] = fma2(av, b23, accv[i][1]);
                accm[i][0] = fma2(am, b01, accm[i][0]);
                accm[i][1] = fma2(am, b23, accm[i][1]);
                accr[i][0] = fma2(ar, a01, accr[i][0]);
                accr[i][1] = fma2(ar, a23, accr[i][1]);
            }
        }
        __syncthreads();
    }

    float bb4[4];
#pragma unroll
    for (int j = 0; j < 4; j++) bb4[j] = bias[n0 + tx * 4 + j];
#pragma unroll
    for (int i = 0; i < 4; i++) {
        const int m = m0 + ty * 4 + i;
        const int bI = m >> 9;          // batch
        const int tI = m & 511;         // time
        const size_t o = ((size_t)tI * 64 + bI) * G4H + n0 + tx * 4;
        float v0, v1, v2, v3, q0, q1, q2, q3, r0, r1, r2, r3;
        upk(accv[i][0], v0, v1); upk(accv[i][1], v2, v3);
        upk(accm[i][0], q0, q1); upk(accm[i][1], q2, q3);
        upk(accr[i][0], r0, r1); upk(accr[i][1], r2, r3);
        *(float4*)(g_Gv + o) = make_float4(v0 + bb4[0], v1 + bb4[1], v2 + bb4[2], v3 + bb4[3]);
        *(float4*)(g_Gl + o) = make_float4(q0 + bb4[0] - r0, q1 + bb4[1] - r1, q2 + bb4[2] - r2, q3 + bb4[3] - r3);
        *(float4*)(g_Gu + o) = make_float4(q0 + bb4[0] + r0, q1 + bb4[1] + r1, q2 + bb4[2] + r2, q3 + bb4[3] + r3);
    }
}

// ---------------------------------------------------------------------------
// Kernel 2: persistent scan.  128 CTAs x 512 thr.
// Thread (kg 0..15, mt 0..31): 2 gate-rows x 8 batches, KSL=16, wreg[2][16].
// gx prefetched 1 step ahead into double-buffered smem.
// ---------------------------------------------------------------------------
#define NCTA 128
#define NTHR 512
#define KSL  16

// smem float offsets
#define SM_H    0        // 6144  : [256 k][24] (hv[8], hm[8], hr[8])
#define SM_RED  6144     // 26624 : u64[512][26] pitch (12+12 used)
#define SM_HALF 32768    // 3584  : u64[128][14]
#define SM_GX   36352    // 3072  : float[2][128 cell][12]
#define SMEM_FLOATS 39424

__global__ __launch_bounds__(NTHR, 1) void scan_kernel(
    const float* __restrict__ Whh, const float* __restrict__ h0,
    const float* __restrict__ c0, float* __restrict__ out)
{
    extern __shared__ float smem[];
    float* sH     = smem + SM_H;
    u64*   sRed   = (u64*)(smem + SM_RED);
    u64*   sHalf  = (u64*)(smem + SM_HALF);
    float* sHalfF = (float*)sHalf;
    float* sGx    = smem + SM_GX;

    const int tid = threadIdx.x;
    const int gb = blockIdx.x >> 4;      // batch group 0..7
    const int hc = blockIdx.x & 15;      // h chunk 0..15
    const int kgr = tid >> 5;            // kgroup 0..15
    const int mt  = tid & 31;            // m-thread 0..31
    const int hLw = mt >> 1;             // 0..15
    const int gp  = mt & 1;              // gate pair 0..1
    const int kbase = kgr * KSL;

    // --- W slices into registers forever: 2 rows x 16 k ---
    float wreg[2][KSL];
#pragma unroll
    for (int r = 0; r < 2; r++) {
        const float* wrow = Whh + (size_t)((gp * 2 + r) * HH + hc * 16 + hLw) * HH + kbase;
#pragma unroll
        for (int i = 0; i < KSL / 4; i++) {
            const float4 w4 = *(const float4*)(wrow + 4 * i);
            wreg[r][4 * i + 0] = w4.x; wreg[r][4 * i + 1] = w4.y;
            wreg[r][4 * i + 2] = w4.z; wreg[r][4 * i + 3] = w4.w;
        }
    }

    // --- pointwise cell state (tid < 128): cell c = tid = ph*8+pb ---
    const int pb = tid & 7;
    const int ph = (tid >> 3) & 15;
    const int bglob = gb * 8 + pb;
    const int hg = hc * 16 + ph;
    float cv = 0.f, cl = 0.f, cu = 0.f;
    if (tid < 128) { cv = c0[bglob * HH + hg]; cl = cv; cu = cv; }

    unsigned int* barp = &g_bar[gb];

    // gx prefetch thread decode (tid < 384)
    const int pw_q  = tid >> 7;          // 0..2 (v,l,u) warp-uniform
    const int pw_b  = (tid >> 4) & 7;
    const int pw_g  = (tid >> 2) & 3;
    const int pw_h4 = tid & 3;
    const float* gq_base = (pw_q == 0) ? g_Gv : (pw_q == 1) ? g_Gl : g_Gu;
    const size_t pw_off = (size_t)(gb * 8 + pw_b) * G4H + pw_g * 256 + hc * 16 + pw_h4 * 4;

    // --- pre-loop: stage h0 and gx(0) ---
    for (int idx = tid; idx < 2048; idx += NTHR) {
        const int k = idx >> 3, bb = idx & 7;
        const float v = h0[(gb * 8 + bb) * HH + k];
        sH[k * 24 + bb]      = v;
        sH[k * 24 + 8 + bb]  = v;
        sH[k * 24 + 16 + bb] = 0.f;
    }
    if (tid < 384) {
        const float4 f = __ldcg((const float4*)(gq_base + pw_off));
        const float ff[4] = {f.x, f.y, f.z, f.w};
#pragma unroll
        for (int i = 0; i < 4; i++)
            sGx[((pw_h4 * 4 + i) * 8 + pw_b) * 12 + pw_q * 4 + pw_g] = ff[i];
    }

    for (int t = 0; t < TT; t++) {
        if (t > 0) {
            if (tid == 0) {
                unsigned int v;
                do {
                    asm volatile("ld.acquire.gpu.global.u32 %0, [%1];" : "=r"(v) : "l"(barp) : "memory");
                } while (v < (unsigned)t * 16u);
            }
            __syncthreads();
            // stage previous h
            const float4* src = g_Hf4 + ((t - 1) & 1) * (HH * BB) + gb * 8;
            for (int idx = tid; idx < 2048; idx += NTHR) {
                const int k = idx >> 3, bb = idx & 7;
                const float4 f = __ldcg(src + k * BB + bb);
                sH[k * 24 + bb]      = f.x;
                sH[k * 24 + 8 + bb]  = f.y;
                sH[k * 24 + 16 + bb] = f.z;
            }
        }
        // prefetch gx(t+1) into the other buffer
        if (t + 1 < TT && tid < 384) {
            const float4 f = __ldcg((const float4*)(gq_base + (size_t)(t + 1) * 64 * G4H + pw_off));
            float* dst = sGx + ((t + 1) & 1) * 1536;
            const float ff[4] = {f.x, f.y, f.z, f.w};
#pragma unroll
            for (int i = 0; i < 4; i++)
                dst[((pw_h4 * 4 + i) * 8 + pw_b) * 12 + pw_q * 4 + pw_g] = ff[i];
        }
        __syncthreads();

        // --- k-loop: 16 iters, 6 broadcast LDS.128, 24 FFMA2, W in regs ---
        u64 A0[12], A1[12];
#pragma unroll
        for (int j = 0; j < 12; j++) { A0[j] = 0ull; A1[j] = 0ull; }
#pragma unroll
        for (int kk = 0; kk < KSL; kk++) {
            const ulonglong2* hk = (const ulonglong2*)(sH + (kbase + kk) * 24);
            const ulonglong2 hva = hk[0];
            const ulonglong2 hvb = hk[1];
            const ulonglong2 hma = hk[2];
            const ulonglong2 hmb = hk[3];
            const ulonglong2 hra = hk[4];
            const ulonglong2 hrb = hk[5];
            {
                const float w = wreg[0][kk];
                const u64 wd = pk(w, w);
                const u64 wa = wd & 0x7FFFFFFF7FFFFFFFull;
                A0[0] = fma2(hva.x, wd, A0[0]);  A0[1] = fma2(hva.y, wd, A0[1]);
                A0[2] = fma2(hvb.x, wd, A0[2]);  A0[3] = fma2(hvb.y, wd, A0[3]);
                A0[4] = fma2(hma.x, wd, A0[4]);  A0[5] = fma2(hma.y, wd, A0[5]);
                A0[6] = fma2(hmb.x, wd, A0[6]);  A0[7] = fma2(hmb.y, wd, A0[7]);
                A0[8] = fma2(hra.x, wa, A0[8]);  A0[9] = fma2(hra.y, wa, A0[9]);
                A0[10] = fma2(hrb.x, wa, A0[10]); A0[11] = fma2(hrb.y, wa, A0[11]);
            }
            {
                const float w = wreg[1][kk];
                const u64 wd = pk(w, w);
                const u64 wa = wd & 0x7FFFFFFF7FFFFFFFull;
                A1[0] = fma2(hva.x, wd, A1[0]);  A1[1] = fma2(hva.y, wd, A1[1]);
                A1[2] = fma2(hvb.x, wd, A1[2]);  A1[3] = fma2(hvb.y, wd, A1[3]);
                A1[4] = fma2(hma.x, wd, A1[4]);  A1[5] = fma2(hma.y, wd, A1[5]);
                A1[6] = fma2(hmb.x, wd, A1[6]);  A1[7] = fma2(hmb.y, wd, A1[7]);
                A1[8] = fma2(hra.x, wa, A1[8]);  A1[9] = fma2(hra.y, wa, A1[9]);
                A1[10] = fma2(hrb.x, wa, A1[10]); A1[11] = fma2(hrb.y, wa, A1[11]);
            }
        }

        // publish partials
        {
            u64* pr = sRed + (size_t)tid * 26;
            ((ulonglong2*)pr)[0] = make_ulonglong2(A0[0], A0[1]);
            ((ulonglong2*)pr)[1] = make_ulonglong2(A0[2], A0[3]);
            ((ulonglong2*)pr)[2] = make_ulonglong2(A0[4], A0[5]);
            ((ulonglong2*)pr)[3] = make_ulonglong2(A0[6], A0[7]);
            ((ulonglong2*)pr)[4] = make_ulonglong2(A0[8], A0[9]);
            ((ulonglong2*)pr)[5] = make_ulonglong2(A0[10], A0[11]);
            ((ulonglong2*)pr)[6] = make_ulonglong2(A1[0], A1[1]);
            ((ulonglong2*)pr)[7] = make_ulonglong2(A1[2], A1[3]);
            ((ulonglong2*)pr)[8] = make_ulonglong2(A1[4], A1[5]);
            ((ulonglong2*)pr)[9] = make_ulonglong2(A1[6], A1[7]);
            ((ulonglong2*)pr)[10] = make_ulonglong2(A1[8], A1[9]);
            ((ulonglong2*)pr)[11] = make_ulonglong2(A1[10], A1[11]);
        }
        __syncthreads();

        // stage B: 128 threads, (m 0..63, half): sum 8 kgroups
        if (tid < 128) {
            const int m  = tid & 63;
            const int hf = tid >> 6;
            const int mtp = (m >> 2) * 2 + ((m & 3) >> 1);   // publisher mt
            const int rsub = m & 1;
            u64 B[12];
#pragma unroll
            for (int j = 0; j < 12; j++) B[j] = 0ull;
#pragma unroll
            for (int s = 0; s < 8; s++) {
                const u64* p = sRed + (size_t)((hf * 8 + s) * 32 + mtp) * 26 + rsub * 12;
#pragma unroll
                for (int j2 = 0; j2 < 6; j2++) {
                    const ulonglong2 q = ((const ulonglong2*)p)[j2];
                    B[2 * j2]     = add2(B[2 * j2], q.x);
                    B[2 * j2 + 1] = add2(B[2 * j2 + 1], q.y);
                }
            }
            u64* po = sHalf + (size_t)(hf * 64 + m) * 14;
#pragma unroll
            for (int j2 = 0; j2 < 6; j2++)
                ((ulonglong2*)po)[j2] = make_ulonglong2(B[2 * j2], B[2 * j2 + 1]);
        }
        __syncthreads();

        // pointwise (tid < 128)
        if (tid < 128) {
            const int c = tid;
            const float* gx = sGx + (t & 1) * 1536 + c * 12;
            float a[4][3];
#pragma unroll
            for (int g = 0; g < 4; g++) {
                const int m = ph * 4 + g;
#pragma unroll
                for (int grp = 0; grp < 3; grp++) {
                    const int ji = grp * 4 + (pb >> 1);
                    const float f0 = sHalfF[((0 * 64 + m) * 14 + ji) * 2 + (pb & 1)];
                    const float f1 = sHalfF[((1 * 64 + m) * 14 + ji) * 2 + (pb & 1)];
                    a[g][grp] = f0 + f1;
                }
            }
            const float pv0 = gx[0] + a[0][0], pl0 = gx[4] + a[0][1] - a[0][2], pu0 = gx[8]  + a[0][1] + a[0][2];
            const float pv1 = gx[1] + a[1][0], pl1 = gx[5] + a[1][1] - a[1][2], pu1 = gx[9]  + a[1][1] + a[1][2];
            const float pv2 = gx[2] + a[2][0], pl2 = gx[6] + a[2][1] - a[2][2], pu2 = gx[10] + a[2][1] + a[2][2];
            const float pv3 = gx[3] + a[3][0], pl3 = gx[7] + a[3][1] - a[3][2], pu3 = gx[11] + a[3][1] + a[3][2];

            const float iv = sigf(pv0), il = sigf(pl0), iu = sigf(pu0);
            const float fv = sigf(pv1), fl = sigf(pl1), fu = sigf(pu1);
            const float gv = tanhf_(pv2), gl = tanhf_(pl2), gu = tanhf_(pu2);
            const float ov = sigf(pv3), ol = sigf(pl3), ou = sigf(pu3);

            const float t1 = fl * cl, t2 = fl * cu, t3 = fu * cl, t4 = fu * cu;
            const float s1 = il * gl, s2 = il * gu, s3 = iu * gl, s4 = iu * gu;
            cv = fv * cv + iv * gv;
            cl = min4f(t1, t2, t3, t4) + min4f(s1, s2, s3, s4);
            cu = max4f(t1, t2, t3, t4) + max4f(s1, s2, s3, s4);

            const float tv = tanhf_(cv), tl = tanhf_(cl), tu = tanhf_(cu);
            const float u1 = ol * tl, u2 = ol * tu, u3 = ou * tl, u4 = ou * tu;
            const float hn_l = min4f(u1, u2, u3, u4);
            const float hn_u = max4f(u1, u2, u3, u4);
            const float hn_v = ov * tv;

            const float hm = 0.5f * (hn_l + hn_u);
            const float hr = 0.5f * (hn_u - hn_l);
            __stcg(g_Hf4 + (t & 1) * (HH * BB) + hg * BB + bglob,
                   make_float4(hn_v, hm, hr, 0.f));
            __syncthreads();                          // (a) all h published
            if (tid == 0)
                asm volatile("red.release.gpu.global.add.u32 [%0], 1;" :: "l"(barp) : "memory");
            // output stores after arrive (off consumers' critical path)
            const size_t obase = ((size_t)(bglob << 9) + t) * HH + hg;
            out[obase] = hn_v;
            out[(size_t)BB * TT * HH + obase] = hn_l;
            out[2 * (size_t)BB * TT * HH + obase] = hn_u;
        } else {
            __syncthreads();
        }
    }
}

// ---------------------------------------------------------------------------
// Launch
// ---------------------------------------------------------------------------
extern "C" void kernel_launch(void* const* d_in, const int* in_sizes, int n_in,
                              void* d_out, int out_size)
{
    const float* xv   = (const float*)d_in[0];
    const float* xl   = (const float*)d_in[1];
    const float* xu   = (const float*)d_in[2];
    const float* Wih  = (const float*)d_in[3];
    const float* Whh  = (const float*)d_in[4];
    const float* bias = (const float*)d_in[5];
    const float* h0   = (const float*)d_in[6];
    const float* c0   = (const float*)d_in[7];
    float* out = (float*)d_out;

    const int smem_bytes = SMEM_FLOATS * sizeof(float);   // ~154 KB
    cudaFuncSetAttribute(scan_kernel, cudaFuncAttributeMaxDynamicSharedMemorySize, smem_bytes);

    gx_gemm_kernel<<<dim3(G4H / GN, (BB * TT) / GM), 256>>>(xv, xl, xu, Wih, bias);
    scan_kernel<<<NCTA, NTHR, smem_bytes>>>(Whh, h0, c0, out);
}